// round 4
// baseline (speedup 1.0000x reference)
#include <cuda_runtime.h>

// Shapes fixed by the problem: B=32, S=4096, H=1024, fp32.
#define BB 32
#define SS 4096
#define HH 1024
#define H4 (HH / 4)              // 256 float4 per row
#define CHUNKS 8                 // 8*32 = 256 CTAs -> ONE full wave at occ 2
#define ROWS_PER (SS / CHUNKS)   // 512 rows per CTA
#define THREADS 256
#define WARPS 8
#define ROWS_PER_WARP (ROWS_PER / WARPS)   // 64
#define K4 (H4 / 32)             // 8 float4 per lane per row
#define EPS 1e-5f

// Scratch (static device arrays: allocation-free).
__device__ float4 g_acc[BB][CHUNKS][H4];   // 1 MiB
__device__ float g_m[BB][CHUNKS];
__device__ float g_l[BB][CHUNKS];
__device__ float g_cmu[BB][CHUNKS];
__device__ unsigned int g_cnt[BB];         // zero-init; reset by merger each launch

// ---------------------------------------------------------------------------
// Single fused kernel. CTA = (chunk c, batch b). Warp w owns rows
// s = w, w+8, ... (64 rows). Lane l covers float4 columns k*32+l, k=0..7.
// All row reductions are warp shuffles -> no barriers in the hot loop.
// The last CTA to finish within a batch merges the 8 partials and writes out.
// ---------------------------------------------------------------------------
__global__ void __launch_bounds__(THREADS, 2)
ln_attn_fused(const float* __restrict__ x,
              const float* __restrict__ gamma,
              const float* __restrict__ beta,
              const float* __restrict__ attw,
              float* __restrict__ out) {
    __shared__ float4 s_gw[H4];          // 4 KB: gamma * attn_w
    __shared__ float  s_red[WARPS];
    __shared__ float  s_m[WARPS], s_l[WARPS], s_cmu[WARPS];
    __shared__ float4 s_acc[WARPS * H4]; // 32 KB: per-warp accumulators
    __shared__ int    s_last;

    const int b = blockIdx.y;
    const int c = blockIdx.x;
    const int t = threadIdx.x;
    const int w = t >> 5;
    const int l = t & 31;

    // gw = gamma * attn_w, and Sgw = sum(gw)
    float4 g4 = reinterpret_cast<const float4*>(gamma)[t];
    float4 w4 = reinterpret_cast<const float4*>(attw)[t];
    float4 gwt;
    gwt.x = g4.x * w4.x; gwt.y = g4.y * w4.y; gwt.z = g4.z * w4.z; gwt.w = g4.w * w4.w;
    s_gw[t] = gwt;
    float sg = gwt.x + gwt.y + gwt.z + gwt.w;
    #pragma unroll
    for (int off = 16; off > 0; off >>= 1) sg += __shfl_xor_sync(0xffffffffu, sg, off);
    if (l == 0) s_red[w] = sg;
    __syncthreads();
    float Sgw = 0.f;
    #pragma unroll
    for (int i = 0; i < WARPS; ++i) Sgw += s_red[i];

    const float4* base = reinterpret_cast<const float4*>(
        x + ((size_t)b * SS + (size_t)c * ROWS_PER) * HH);

    float m = -1e30f, lacc = 0.f, cmu = 0.f;
    float4 acc[K4];
    #pragma unroll
    for (int k = 0; k < K4; ++k) acc[k] = make_float4(0.f, 0.f, 0.f, 0.f);

    // prefetch first row of this warp
    float4 xc[K4], xn[K4];
    {
        const float4* rp = base + (size_t)w * H4;
        #pragma unroll
        for (int k = 0; k < K4; ++k) xc[k] = rp[k * 32 + l];
    }

    const float inv_h = 1.f / (float)HH;
    for (int i = 0; i < ROWS_PER_WARP; ++i) {
        // issue next row's loads early (double buffer)
        if (i + 1 < ROWS_PER_WARP) {
            const float4* rp = base + ((size_t)w + (size_t)(i + 1) * WARPS) * H4;
            #pragma unroll
            for (int k = 0; k < K4; ++k) xn[k] = rp[k * 32 + l];
        }

        float sum = 0.f, ssq = 0.f, dot = 0.f;
        #pragma unroll
        for (int k = 0; k < K4; ++k) {
            float4 v = xc[k];
            float4 gw = s_gw[k * 32 + l];
            sum += v.x + v.y + v.z + v.w;
            ssq += v.x * v.x + v.y * v.y + v.z * v.z + v.w * v.w;
            dot += v.x * gw.x + v.y * gw.y + v.z * gw.z + v.w * gw.w;
        }
        #pragma unroll
        for (int off = 16; off > 0; off >>= 1) {
            sum += __shfl_xor_sync(0xffffffffu, sum, off);
            ssq += __shfl_xor_sync(0xffffffffu, ssq, off);
            dot += __shfl_xor_sync(0xffffffffu, dot, off);
        }

        float mu   = sum * inv_h;
        float var  = ssq * inv_h - mu * mu;
        float rstd = rsqrtf(var + EPS);
        float score = rstd * (dot - mu * Sgw);

        if (score > m) {
            float sc = __expf(m - score);    // 0 on first iteration
            lacc *= sc; cmu *= sc;
            #pragma unroll
            for (int k = 0; k < K4; ++k) {
                acc[k].x *= sc; acc[k].y *= sc; acc[k].z *= sc; acc[k].w *= sc;
            }
            m = score;
        }
        float p  = __expf(score - m);
        float pr = p * rstd;
        lacc += p;
        cmu  += pr * mu;
        #pragma unroll
        for (int k = 0; k < K4; ++k) {
            acc[k].x += pr * xc[k].x; acc[k].y += pr * xc[k].y;
            acc[k].z += pr * xc[k].z; acc[k].w += pr * xc[k].w;
        }

        #pragma unroll
        for (int k = 0; k < K4; ++k) xc[k] = xn[k];
    }

    // merge 8 warp partials within the CTA
    #pragma unroll
    for (int k = 0; k < K4; ++k) s_acc[w * H4 + k * 32 + l] = acc[k];
    if (l == 0) { s_m[w] = m; s_l[w] = lacc; s_cmu[w] = cmu; }
    __syncthreads();

    float M = -1e30f;
    #pragma unroll
    for (int wp = 0; wp < WARPS; ++wp) M = fmaxf(M, s_m[wp]);
    float L = 0.f, CMU = 0.f, ew[WARPS];
    #pragma unroll
    for (int wp = 0; wp < WARPS; ++wp) {
        ew[wp] = __expf(s_m[wp] - M);
        L   += s_l[wp]   * ew[wp];
        CMU += s_cmu[wp] * ew[wp];
    }
    float4 A = make_float4(0.f, 0.f, 0.f, 0.f);
    #pragma unroll
    for (int wp = 0; wp < WARPS; ++wp) {
        float4 a = s_acc[wp * H4 + t];
        float e = ew[wp];
        A.x += a.x * e; A.y += a.y * e; A.z += a.z * e; A.w += a.w * e;
    }
    g_acc[b][c][t] = A;
    if (t == 0) { g_m[b][c] = M; g_l[b][c] = L; g_cmu[b][c] = CMU; }

    // -------- last CTA of this batch merges the CHUNKS partials --------
    __threadfence();             // release: make partials visible
    __syncthreads();             // all stores issued before the vote
    if (t == 0)
        s_last = (atomicAdd(&g_cnt[b], 1u) == CHUNKS - 1);
    __syncthreads();
    if (!s_last) return;

    __threadfence();             // acquire: order reads after the count

    float Mg = -1e30f;
    #pragma unroll
    for (int cc = 0; cc < CHUNKS; ++cc) Mg = fmaxf(Mg, g_m[b][cc]);
    float Lg = 0.f, CMg = 0.f, ec[CHUNKS];
    #pragma unroll
    for (int cc = 0; cc < CHUNKS; ++cc) {
        ec[cc] = __expf(g_m[b][cc] - Mg);
        Lg  += g_l[b][cc]   * ec[cc];
        CMg += g_cmu[b][cc] * ec[cc];
    }
    float4 T = make_float4(0.f, 0.f, 0.f, 0.f);
    #pragma unroll
    for (int cc = 0; cc < CHUNKS; ++cc) {
        float4 a = g_acc[b][cc][t];
        float e = ec[cc];
        T.x += a.x * e; T.y += a.y * e; T.z += a.z * e; T.w += a.w * e;
    }
    const float inv = 1.f / Lg;
    float4 b4 = reinterpret_cast<const float4*>(beta)[t];
    float4 o;
    o.x = g4.x * (T.x - CMg) * inv + b4.x;
    o.y = g4.y * (T.y - CMg) * inv + b4.y;
    o.z = g4.z * (T.z - CMg) * inv + b4.z;
    o.w = g4.w * (T.w - CMg) * inv + b4.w;
    reinterpret_cast<float4*>(out + (size_t)b * HH)[t] = o;

    if (t == 0) g_cnt[b] = 0;    // reset for next graph replay
}

extern "C" void kernel_launch(void* const* d_in, const int* in_sizes, int n_in,
                              void* d_out, int out_size) {
    const float* x     = (const float*)d_in[0];   // [B,S,H]
    const float* gamma = (const float*)d_in[1];   // [H]
    const float* beta  = (const float*)d_in[2];   // [H]
    const float* attw  = (const float*)d_in[3];   // [H]
    float* out = (float*)d_out;                   // [B,H]
    (void)in_sizes; (void)n_in; (void)out_size;

    dim3 grid(CHUNKS, BB);
    ln_attn_fused<<<grid, THREADS>>>(x, gamma, beta, attw, out);
}